// round 16
// baseline (speedup 1.0000x reference)
#include <cuda_runtime.h>
#include <cuda_bf16.h>
#include <cstdint>

#define Bb_  16
#define N1_  4096
#define N2_  1024
#define C1_  128
#define C2_  256
#define K0_  384
#define M0_  256
#define M1_  128
#define KNN_ 3
#define EPSD 1e-10f
#define BNEPS 1e-5f

#define BK 32
#define NSTAGE 3
#define A_STR 80u
#define NSLOT0 512    // GEMM0: 16 b x 32 n-tiles
#define NSLOT1 256    // GEMM1: 16 b x 16 n-tiles

// ---------------- scratch ----------------------------------------------------
__device__ int   g_idx[Bb_ * N1_ * KNN_];
__device__ float g_w  [Bb_ * N1_ * KNN_];
__device__ float g_p2t[(size_t)Bb_ * N2_ * C2_];
__device__ float g_y0 [(size_t)Bb_ * M0_ * N1_];
__device__ __nv_bfloat16 g_x0h[(size_t)Bb_ * K0_ * N1_];
__device__ __nv_bfloat16 g_x0l[(size_t)Bb_ * K0_ * N1_];
__device__ float g_partS[M0_ * NSLOT0];
__device__ float g_partQ[M0_ * NSLOT0];
__device__ float g_scale0[M0_], g_shift0[M0_];
__device__ float g_scale1[M1_], g_shift1[M1_];
__device__ __nv_bfloat16 g_w0h[M0_ * K0_], g_w0l[M0_ * K0_];
__device__ __nv_bfloat16 g_w1h[M1_ * M0_], g_w1l[M1_ * M0_];

// ---------------- helpers -----------------------------------------------------
__device__ __forceinline__ uint32_t smem_u32(const void* p) {
    uint32_t a;
    asm("{ .reg .u64 t; cvta.to.shared.u64 t, %1; cvt.u32.u64 %0, t; }" : "=r"(a) : "l"(p));
    return a;
}
__device__ __forceinline__ void cp16(uint32_t dst, const void* src) {
    asm volatile("cp.async.cg.shared.global [%0], [%1], 16;" :: "r"(dst), "l"(src));
}
__device__ __forceinline__ void cp_commit() { asm volatile("cp.async.commit_group;" ::: "memory"); }
__device__ __forceinline__ void cp_wait1()  { asm volatile("cp.async.wait_group 1;" ::: "memory"); }
__device__ __forceinline__ void ldsm_x4(uint32_t* r, uint32_t addr) {
    asm volatile("ldmatrix.sync.aligned.m8n8.x4.shared.b16 {%0,%1,%2,%3}, [%4];"
                 : "=r"(r[0]), "=r"(r[1]), "=r"(r[2]), "=r"(r[3]) : "r"(addr));
}
__device__ __forceinline__ void ldsm_x4t(uint32_t* r, uint32_t addr) {
    asm volatile("ldmatrix.sync.aligned.m8n8.x4.trans.shared.b16 {%0,%1,%2,%3}, [%4];"
                 : "=r"(r[0]), "=r"(r[1]), "=r"(r[2]), "=r"(r[3]) : "r"(addr));
}
__device__ __forceinline__ void mma_bf16(float* d, const uint32_t* a, const uint32_t* b) {
    asm volatile("mma.sync.aligned.m16n8k16.row.col.f32.bf16.bf16.f32 "
                 "{%0,%1,%2,%3}, {%4,%5,%6,%7}, {%8,%9}, {%0,%1,%2,%3};"
                 : "+f"(d[0]), "+f"(d[1]), "+f"(d[2]), "+f"(d[3])
                 : "r"(a[0]), "r"(a[1]), "r"(a[2]), "r"(a[3]), "r"(b[0]), "r"(b[1]));
}
__device__ __forceinline__ uint32_t split_pack(float x0, float x1, uint32_t& lw) {
    __nv_bfloat16 h0 = __float2bfloat16_rn(x0);
    __nv_bfloat16 h1 = __float2bfloat16_rn(x1);
    __nv_bfloat16 l0 = __float2bfloat16_rn(x0 - __bfloat162float(h0));
    __nv_bfloat16 l1 = __float2bfloat16_rn(x1 - __bfloat162float(h1));
    lw = (uint32_t)__bfloat16_as_ushort(l0) | ((uint32_t)__bfloat16_as_ushort(l1) << 16);
    return (uint32_t)__bfloat16_as_ushort(h0) | ((uint32_t)__bfloat16_as_ushort(h1) << 16);
}

// ---------------- kernel 1: 3-NN (2 points per thread) -----------------------
__global__ void __launch_bounds__(128) knn_kernel(const float* __restrict__ xyz1,
                                                  const float* __restrict__ xyz2)
{
    __shared__ float sx[N2_], sy[N2_], sz[N2_], ss[N2_];
    const int b = blockIdx.y;
    const float* p2 = xyz2 + (size_t)b * N2_ * 3;
    for (int j = threadIdx.x; j < N2_; j += blockDim.x) {
        float x = p2[j*3+0], y = p2[j*3+1], z = p2[j*3+2];
        sx[j] = x; sy[j] = y; sz[j] = z; ss[j] = x*x + y*y + z*z;
    }
    __syncthreads();

    const int na = blockIdx.x * 256 + threadIdx.x;
    const int nb = na + 128;
    const float* pa = xyz1 + ((size_t)b * N1_ + na) * 3;
    const float* pb = xyz1 + ((size_t)b * N1_ + nb) * 3;
    const float xa = pa[0], ya = pa[1], za = pa[2];
    const float xb = pb[0], yb = pb[1], zb = pb[2];
    const float s1a = xa*xa + ya*ya + za*za;
    const float s1b = xb*xb + yb*yb + zb*zb;

    float a0 = 3.0e38f, a1 = 3.0e38f, a2 = 3.0e38f;
    float b0 = 3.0e38f, b1 = 3.0e38f, b2 = 3.0e38f;
    int   ia0 = 0, ia1 = 0, ia2 = 0;
    int   ib0 = 0, ib1 = 0, ib2 = 0;
    #pragma unroll 4
    for (int j = 0; j < N2_; j++) {
        const float cx = sx[j], cy = sy[j], cz = sz[j], cs = ss[j];
        float da = fmaxf(s1a + cs - 2.0f * (xa*cx + ya*cy + za*cz), EPSD);
        float db = fmaxf(s1b + cs - 2.0f * (xb*cx + yb*cy + zb*cz), EPSD);
        if (da < a2) {
            if (da < a1) {
                a2 = a1; ia2 = ia1;
                if (da < a0) { a1 = a0; ia1 = ia0; a0 = da; ia0 = j; }
                else         { a1 = da; ia1 = j; }
            } else { a2 = da; ia2 = j; }
        }
        if (db < b2) {
            if (db < b1) {
                b2 = b1; ib2 = ib1;
                if (db < b0) { b1 = b0; ib1 = ib0; b0 = db; ib0 = j; }
                else         { b1 = db; ib1 = j; }
            } else { b2 = db; ib2 = j; }
        }
    }
    {
        float w0 = 1.0f/a0, w1 = 1.0f/a1, w2 = 1.0f/a2;
        float inv = 1.0f / (w0 + w1 + w2);
        size_t base = ((size_t)b * N1_ + na) * KNN_;
        g_idx[base+0] = ia0; g_idx[base+1] = ia1; g_idx[base+2] = ia2;
        g_w  [base+0] = w0*inv; g_w[base+1] = w1*inv; g_w[base+2] = w2*inv;
    }
    {
        float w0 = 1.0f/b0, w1 = 1.0f/b1, w2 = 1.0f/b2;
        float inv = 1.0f / (w0 + w1 + w2);
        size_t base = ((size_t)b * N1_ + nb) * KNN_;
        g_idx[base+0] = ib0; g_idx[base+1] = ib1; g_idx[base+2] = ib2;
        g_w  [base+0] = w0*inv; g_w[base+1] = w1*inv; g_w[base+2] = w2*inv;
    }
}

// ---------------- kernel 1b: transpose points2 (C2,N2) -> (N2,C2) -----------
__global__ void __launch_bounds__(256) transpose_kernel(const float* __restrict__ src)
{
    __shared__ float tile[32][33];
    const int b  = blockIdx.z;
    const int n0 = blockIdx.x * 32;
    const int c0 = blockIdx.y * 32;
    const int tx = threadIdx.x & 31, ty = threadIdx.x >> 5;
    const float* s = src + (size_t)b * C2_ * N2_;
    #pragma unroll
    for (int i = 0; i < 4; i++)
        tile[ty + i*8][tx] = s[(size_t)(c0 + ty + i*8) * N2_ + n0 + tx];
    __syncthreads();
    float* d = g_p2t + (size_t)b * N2_ * C2_;
    #pragma unroll
    for (int i = 0; i < 4; i++)
        d[(size_t)(n0 + ty + i*8) * C2_ + c0 + tx] = tile[tx][ty + i*8];
}

// ---------------- kernel 2: interpolate (point-major gathers) ----------------
__global__ void __launch_bounds__(256) interp_kernel()
{
    __shared__ uint16_t shh[256][34];
    __shared__ uint16_t shl[256][34];
    __shared__ int   sj[96];
    __shared__ float swt[96];

    const int b  = blockIdx.y;
    const int n0 = blockIdx.x * 32;
    const int t  = threadIdx.x;
    const int lane = t & 31, w = t >> 5;

    if (t < 96) {
        const size_t kb = ((size_t)b * N1_ + n0) * KNN_;
        sj[t]  = g_idx[kb + t];
        swt[t] = g_w[kb + t];
    }
    __syncthreads();

    #pragma unroll
    for (int it = 0; it < 4; it++) {
        const int p = w + it * 8;
        const int   j0 = sj[p*3],  j1 = sj[p*3+1],  j2 = sj[p*3+2];
        const float w0 = swt[p*3], w1 = swt[p*3+1], w2 = swt[p*3+2];
        const float* r0 = g_p2t + ((size_t)b * N2_ + j0) * C2_;
        const float* r1 = g_p2t + ((size_t)b * N2_ + j1) * C2_;
        const float* r2 = g_p2t + ((size_t)b * N2_ + j2) * C2_;
        #pragma unroll
        for (int i = 0; i < 8; i++) {
            const int c = i * 32 + lane;
            float v = w0 * r0[c] + w1 * r1[c] + w2 * r2[c];
            __nv_bfloat16 h  = __float2bfloat16_rn(v);
            __nv_bfloat16 lo = __float2bfloat16_rn(v - __bfloat162float(h));
            shh[c][p] = __bfloat16_as_ushort(h);
            shl[c][p] = __bfloat16_as_ushort(lo);
        }
    }
    __syncthreads();

    #pragma unroll 4
    for (int k = 0; k < 32; k++) {
        const int c = w * 32 + k;
        const size_t di = ((size_t)b * K0_ + C1_ + c) * N1_ + n0 + lane;
        g_x0h[di] = __ushort_as_bfloat16(shh[c][lane]);
        g_x0l[di] = __ushort_as_bfloat16(shl[c][lane]);
    }
}

// ---------------- kernel 2a: points1 -> x0 rows [0..128) as bf16 h/l ---------
__global__ void __launch_bounds__(256) convp1_kernel(const float* __restrict__ points1)
{
    const int idx = blockIdx.x * 256 + threadIdx.x;
    const int total4 = Bb_ * C1_ * (N1_/4);
    if (idx >= total4) return;
    const int n4 = idx & 1023;
    const int c  = (idx >> 10) & (C1_ - 1);
    const int b  = idx >> 17;
    float4 v = *(const float4*)(points1 + (((size_t)b * C1_ + c) * N1_) + n4*4);
    uint32_t h0, h1, l0, l1;
    h0 = split_pack(v.x, v.y, l0);
    h1 = split_pack(v.z, v.w, l1);
    const size_t di = ((size_t)b * K0_ + c) * N1_ + n4*4;
    *(uint2*)(g_x0h + di) = make_uint2(h0, h1);
    *(uint2*)(g_x0l + di) = make_uint2(l0, l1);
}

// ---------------- kernel 2b: split weights fp32 -> bf16 hi/lo ----------------
__global__ void __launch_bounds__(256) splitw_kernel(const float* __restrict__ W0,
                                                     const float* __restrict__ W1)
{
    const int i = blockIdx.x * 256 + threadIdx.x;
    if (i < M0_ * K0_) {
        float v = W0[i];
        __nv_bfloat16 h = __float2bfloat16_rn(v);
        g_w0h[i] = h;
        g_w0l[i] = __float2bfloat16_rn(v - __bfloat162float(h));
    }
    if (i < M1_ * M0_) {
        float v = W1[i];
        __nv_bfloat16 h = __float2bfloat16_rn(v);
        g_w1h[i] = h;
        g_w1l[i] = __float2bfloat16_rn(v - __bfloat162float(h));
    }
}

// ---------------- kernel 3: split-bf16 mma.sync GEMM, tile-templated ---------
// BMT x BNT CTA tile, 8 warps of 64x64 (warp grid (BMT/64) x (BNT/64)).
// BN_IN=false: B staged via cp.async from bf16 h/l. BN_IN=true: B staged from
// fp32 Xf with fused BN+ReLU+split (GEMM1 only; BNT=256 constants).
template<bool BN_IN, int BMT, int BNT>
__global__ void __launch_bounds__(256, 1) mma_gemm(
    const __nv_bfloat16* __restrict__ Wh, const __nv_bfloat16* __restrict__ Wl,
    int Mdim, int Kdim,
    const __nv_bfloat16* __restrict__ Xh, const __nv_bfloat16* __restrict__ Xl,
    const float* __restrict__ Xf,
    const float* __restrict__ bnsc, const float* __restrict__ bnsh,
    const float* __restrict__ bias,
    float* __restrict__ Y)
{
    constexpr int NWN   = BNT / 64;                   // warps along n
    constexpr uint32_t B_STRT = (uint32_t)(BNT * 2 + 16);
    constexpr uint32_t SZ_AT  = (uint32_t)BMT * A_STR;
    constexpr uint32_t SZ_BT  = 32u * B_STRT;
    constexpr uint32_t OFF_AL = SZ_AT;
    constexpr uint32_t OFF_BH = 2u * SZ_AT;
    constexpr uint32_t OFF_BL = OFF_BH + SZ_BT;
    constexpr uint32_t BUF_SZ = 2u * SZ_AT + 2u * SZ_BT;
    constexpr int AQ = BMT / 64;                      // A cp16 iters per thread
    constexpr int BQ = BNT / 64;                      // B cp16 iters per thread
    constexpr int BROWSH = (BNT == 256) ? 5 : 4;      // log2(BNT/8)

    extern __shared__ __align__(16) char sm[];
    const uint32_t sbase = smem_u32(sm);

    const int tid = threadIdx.x;
    const int lane = tid & 31, wid = tid >> 5;
    const int wm = wid / NWN, wn = wid % NWN;
    const int bb = blockIdx.z;
    const int n0 = blockIdx.x * BNT;
    const size_t xbase = (size_t)bb * Kdim * N1_;
    const int T = Kdim / BK;

    auto stage = [&](int t, int buf) {
        const int kt = t * BK;
        const uint32_t bufb = sbase + (uint32_t)buf * BUF_SZ;
        #pragma unroll
        for (int q = 0; q < AQ; q++) {
            const int c = tid + q * 256;
            const int row = c >> 2, off = c & 3;
            const size_t so = (size_t)row * Kdim + kt + off * 8;
            const uint32_t dd = bufb + (uint32_t)row * A_STR + off * 16;
            cp16(dd,          Wh + so);
            cp16(dd + OFF_AL, Wl + so);
        }
        if (!BN_IN) {
            #pragma unroll
            for (int q = 0; q < BQ; q++) {
                const int c = tid + q * 256;
                const int row = c >> BROWSH, off = c & ((1 << BROWSH) - 1);
                const size_t so = xbase + (size_t)(kt + row) * N1_ + n0 + off * 8;
                const uint32_t dd = bufb + OFF_BH + (uint32_t)row * B_STRT + off * 16;
                cp16(dd,                     Xh + so);
                cp16(dd + (OFF_BL - OFF_BH), Xl + so);
            }
        }
        cp_commit();
    };

    // BN path (BNT=256 only): register B staging + fused BN/ReLU/split
    float vreg[32];
    const int br  = tid >> 3;
    const int bc0 = (tid & 7) * 4;
    auto ldB_bn = [&](int t) {
        if (!BN_IN || t >= T) return;
        const float* src = Xf + xbase + (size_t)(t * BK + br) * N1_ + n0 + bc0;
        #pragma unroll
        for (int q = 0; q < 8; q++)
            *(float4*)(vreg + 4*q) = *(const float4*)(src + q * 32);
    };
    auto stB_bn = [&](int t, int buf) {
        if (!BN_IN || t >= T) return;
        const int k = t * BK + br;
        const float sc = bnsc[k], so = bnsh[k];
        char* dh = sm + (size_t)buf * BUF_SZ + OFF_BH + (size_t)br * B_STRT + (tid & 7) * 8;
        #pragma unroll
        for (int q = 0; q < 8; q++) {
            float x0 = fmaxf(fmaf(sc, vreg[4*q+0], so), 0.0f);
            float x1 = fmaxf(fmaf(sc, vreg[4*q+1], so), 0.0f);
            float x2 = fmaxf(fmaf(sc, vreg[4*q+2], so), 0.0f);
            float x3 = fmaxf(fmaf(sc, vreg[4*q+3], so), 0.0f);
            uint32_t l0, l1;
            uint32_t h0 = split_pack(x0, x1, l0);
            uint32_t h1 = split_pack(x2, x3, l1);
            *(uint2*)(dh + q*64)                     = make_uint2(h0, h1);
            *(uint2*)(dh + q*64 + (OFF_BL - OFF_BH)) = make_uint2(l0, l1);
        }
    };

    float acc[4][8][4];
    #pragma unroll
    for (int i = 0; i < 4; i++)
        #pragma unroll
        for (int j = 0; j < 8; j++)
            #pragma unroll
            for (int q = 0; q < 4; q++) acc[i][j][q] = 0.0f;

    const uint32_t a_rowoff = (uint32_t)(wm*64 + (lane & 15)) * A_STR + ((lane >> 4) * 16);
    const uint32_t b_rowoff = (uint32_t)(lane & 15) * B_STRT + (uint32_t)wn*128 + ((lane >> 4) * 16);

    stage(0, 0);
    stage(1, 1);
    if (BN_IN) {
        ldB_bn(0); stB_bn(0, 0);
        ldB_bn(1);
    }

    for (int t = 0; t < T; t++) {
        cp_wait1();
        __syncthreads();
        if (t + 2 < T) stage(t + 2, (t + 2) % NSTAGE);
        else           cp_commit();
        if (BN_IN) {
            stB_bn(t + 1, (t + 1) % NSTAGE);
            ldB_bn(t + 2);
        }

        const uint32_t cb = sbase + (uint32_t)(t % NSTAGE) * BUF_SZ;
        #pragma unroll
        for (int kh = 0; kh < 2; kh++) {
            uint32_t ah[4][4], al[4][4];
            #pragma unroll
            for (int i = 0; i < 4; i++) {
                const uint32_t addr = cb + a_rowoff + (uint32_t)i*16*A_STR + kh*32;
                ldsm_x4(ah[i], addr);
                ldsm_x4(al[i], addr + OFF_AL);
            }
            #pragma unroll
            for (int j2 = 0; j2 < 4; j2++) {
                uint32_t rh[4], rl[4];
                const uint32_t baddr = cb + OFF_BH + b_rowoff + (uint32_t)kh*16*B_STRT + j2*32;
                ldsm_x4t(rh, baddr);
                ldsm_x4t(rl, baddr + (OFF_BL - OFF_BH));
                #pragma unroll
                for (int i = 0; i < 4; i++) {
                    mma_bf16(acc[i][2*j2],   ah[i], rh);
                    mma_bf16(acc[i][2*j2],   al[i], rh);
                    mma_bf16(acc[i][2*j2],   ah[i], rl);
                    mma_bf16(acc[i][2*j2+1], ah[i], rh + 2);
                    mma_bf16(acc[i][2*j2+1], al[i], rh + 2);
                    mma_bf16(acc[i][2*j2+1], ah[i], rl + 2);
                }
            }
        }
        __syncthreads();
    }

    // ---- epilogue: bias add + fp32 store + per-row partial stats ----
    float* SS = (float*)sm;                  // [NWN][BMT] sums (512 floats)
    float* SQ = (float*)sm + NWN*BMT;        // [NWN][BMT] sumsq

    #pragma unroll
    for (int i = 0; i < 4; i++) {
        const int lr0 = wm*64 + i*16 + (lane >> 2);
        const int r1i = lr0 + 8;
        const float bv0 = bias[lr0], bv1 = bias[r1i];
        float* y0p = Y + ((size_t)bb * Mdim + lr0) * N1_ + n0 + wn*64;
        float* y1p = Y + ((size_t)bb * Mdim + r1i) * N1_ + n0 + wn*64;
        float sa = 0.f, qa = 0.f, sb = 0.f, qb = 0.f;
        #pragma unroll
        for (int j = 0; j < 8; j++) {
            const int nc = j*8 + (lane & 3)*2;
            float v0 = acc[i][j][0] + bv0, v1 = acc[i][j][1] + bv0;
            float v2 = acc[i][j][2] + bv1, v3 = acc[i][j][3] + bv1;
            *(float2*)(y0p + nc) = make_float2(v0, v1);
            *(float2*)(y1p + nc) = make_float2(v2, v3);
            sa += v0 + v1; qa += v0*v0 + v1*v1;
            sb += v2 + v3; qb += v2*v2 + v3*v3;
        }
        #pragma unroll
        for (int o = 1; o < 4; o <<= 1) {
            sa += __shfl_xor_sync(0xffffffffu, sa, o);
            qa += __shfl_xor_sync(0xffffffffu, qa, o);
            sb += __shfl_xor_sync(0xffffffffu, sb, o);
            qb += __shfl_xor_sync(0xffffffffu, qb, o);
        }
        if ((lane & 3) == 0) {
            SS[wn*BMT + lr0]     = sa;  SQ[wn*BMT + lr0]     = qa;
            SS[wn*BMT + lr0 + 8] = sb;  SQ[wn*BMT + lr0 + 8] = qb;
        }
    }
    __syncthreads();
    if (tid < BMT) {
        float s = 0.f, q = 0.f;
        #pragma unroll
        for (int w = 0; w < NWN; w++) { s += SS[w*BMT + tid]; q += SQ[w*BMT + tid]; }
        const int nslot = Bb_ * (N1_ / BNT);
        const int slot = bb * (N1_ / BNT) + blockIdx.x;
        g_partS[(size_t)tid * nslot + slot] = s;
        g_partQ[(size_t)tid * nslot + slot] = q;
    }
}

// ---------------- kernel 4: finalize scale/shift (block per channel) ---------
__global__ void __launch_bounds__(256) stats_final_kernel(const float* __restrict__ gamma,
                                                          const float* __restrict__ beta,
                                                          int layer, int nslot)
{
    const int c = blockIdx.x;
    const int t = threadIdx.x;
    __shared__ float sh[256], sh2[256];
    float s  = g_partS[(size_t)c * nslot + t];
    float s2 = g_partQ[(size_t)c * nslot + t];
    if (nslot > 256) {
        s  += g_partS[(size_t)c * nslot + 256 + t];
        s2 += g_partQ[(size_t)c * nslot + 256 + t];
    }
    sh[t] = s; sh2[t] = s2;
    __syncthreads();
    for (int o = 128; o > 0; o >>= 1) {
        if (t < o) { sh[t] += sh[t + o]; sh2[t] += sh2[t + o]; }
        __syncthreads();
    }
    if (t == 0) {
        const float cnt = (float)(Bb_ * N1_);
        float m = sh[0] / cnt;
        float v = sh2[0] / cnt - m * m;
        float r = rsqrtf(v + BNEPS);
        float a = gamma[c] * r;
        if (layer == 0) { g_scale0[c] = a; g_shift0[c] = beta[c] - a * m; }
        else            { g_scale1[c] = a; g_shift1[c] = beta[c] - a * m; }
    }
}

// ---------------- kernel 5: BN1 + ReLU in place ------------------------------
__global__ void __launch_bounds__(256) bnrelu_kernel(float* __restrict__ Yv, int Mdim)
{
    const size_t total4 = (size_t)Bb_ * Mdim * N1_ / 4;
    const size_t i = (size_t)blockIdx.x * blockDim.x + threadIdx.x;
    if (i >= total4) return;
    const int c = (int)((i >> 10) % Mdim);
    const float a  = g_scale1[c];
    const float sh = g_shift1[c];
    float4 v = ((float4*)Yv)[i];
    v.x = fmaxf(fmaf(a, v.x, sh), 0.0f);
    v.y = fmaxf(fmaf(a, v.y, sh), 0.0f);
    v.z = fmaxf(fmaf(a, v.z, sh), 0.0f);
    v.w = fmaxf(fmaf(a, v.w, sh), 0.0f);
    ((float4*)Yv)[i] = v;
}

// ---------------- launch ------------------------------------------------------
extern "C" void kernel_launch(void* const* d_in, const int* in_sizes, int n_in,
                              void* d_out, int out_size)
{
    const float* xyz1    = (const float*)d_in[0];
    const float* xyz2    = (const float*)d_in[1];
    const float* points1 = (const float*)d_in[2];
    const float* points2 = (const float*)d_in[3];
    const float* W0 = (const float*)d_in[4];
    const float* b0 = (const float*)d_in[5];
    const float* g0 = (const float*)d_in[6];
    const float* be0= (const float*)d_in[7];
    const float* W1 = (const float*)d_in[8];
    const float* b1 = (const float*)d_in[9];
    const float* g1 = (const float*)d_in[10];
    const float* be1= (const float*)d_in[11];
    float* out = (float*)d_out;

    void* p;
    cudaGetSymbolAddress(&p, g_y0);      float* y0 = (float*)p;
    cudaGetSymbolAddress(&p, g_x0h);     __nv_bfloat16* x0h = (__nv_bfloat16*)p;
    cudaGetSymbolAddress(&p, g_x0l);     __nv_bfloat16* x0l = (__nv_bfloat16*)p;
    cudaGetSymbolAddress(&p, g_w0h);     __nv_bfloat16* w0h = (__nv_bfloat16*)p;
    cudaGetSymbolAddress(&p, g_w0l);     __nv_bfloat16* w0l = (__nv_bfloat16*)p;
    cudaGetSymbolAddress(&p, g_w1h);     __nv_bfloat16* w1h = (__nv_bfloat16*)p;
    cudaGetSymbolAddress(&p, g_w1l);     __nv_bfloat16* w1l = (__nv_bfloat16*)p;
    cudaGetSymbolAddress(&p, g_scale0);  float* sc0 = (float*)p;
    cudaGetSymbolAddress(&p, g_shift0);  float* sh0 = (float*)p;

    // smem sizes per instantiation
    const unsigned SMEM0 = NSTAGE * (2u*(256u*A_STR) + 2u*(32u*(128u*2u+16u)));  // 256x128
    const unsigned SMEM1 = NSTAGE * (2u*(128u*A_STR) + 2u*(32u*(256u*2u+16u)));  // 128x256
    cudaFuncSetAttribute((const void*)mma_gemm<false,256,128>, cudaFuncAttributeMaxDynamicSharedMemorySize, SMEM0);
    cudaFuncSetAttribute((const void*)mma_gemm<true,128,256>,  cudaFuncAttributeMaxDynamicSharedMemorySize, SMEM1);

    // 0. prep
    splitw_kernel<<<(M0_*K0_ + 255)/256, 256>>>(W0, W1);
    transpose_kernel<<<dim3(N2_/32, C2_/32, Bb_), 256>>>(points2);
    knn_kernel<<<dim3(N1_/256, Bb_), 128>>>(xyz1, xyz2);
    convp1_kernel<<<(Bb_*C1_*(N1_/4) + 255)/256, 256>>>(points1);
    interp_kernel<<<dim3(N1_/32, Bb_), 256>>>();

    // 1. GEMM0 (256m x 128n; B read once) + fused stats -> y0
    mma_gemm<false,256,128><<<dim3(N1_/128, 1, Bb_), 256, SMEM0>>>(
        w0h, w0l, M0_, K0_, x0h, x0l, nullptr, nullptr, nullptr, b0, y0);

    // 2. finalize BN0 (512 slots)
    stats_final_kernel<<<M0_, 256>>>(g0, be0, 0, NSLOT0);

    // 3. GEMM1 (128m x 256n) with fused BN0+ReLU+split input + fused stats -> out
    mma_gemm<true,128,256><<<dim3(N1_/256, 1, Bb_), 256, SMEM1>>>(
        w1h, w1l, M1_, M0_, nullptr, nullptr, y0, sc0, sh0, b1, out);

    // 4. finalize BN1 (256 slots) + apply in place
    stats_final_kernel<<<M1_, 256>>>(g1, be1, 1, NSLOT1);
    {
        size_t total4 = (size_t)Bb_ * M1_ * N1_ / 4;
        bnrelu_kernel<<<(unsigned)((total4 + 255) / 256), 256>>>(out, M1_);
    }
}

// round 17
// speedup vs baseline: 1.0243x; 1.0243x over previous
#include <cuda_runtime.h>
#include <cuda_bf16.h>
#include <cstdint>

#define Bb_  16
#define N1_  4096
#define N2_  1024
#define C1_  128
#define C2_  256
#define K0_  384
#define M0_  256
#define M1_  128
#define KNN_ 3
#define EPSD 1e-10f
#define BNEPS 1e-5f

#define BK 32
#define NSTAGE 3
#define A_STR 80u
#define NSLOT 256     // 16 batches x 16 n-tiles (BNT=256)

// prep kernel role ranges
#define KNN_BLKS  (Bb_ * (N1_/512))               // 128
#define TR_BLKS   (Bb_ * (C2_/32) * (N2_/32))     // 4096
#define CP1_BLKS  ((Bb_*C1_*(N1_/4))/256)         // 8192
#define SW_BLKS   ((M0_*K0_ + 255)/256)           // 384
#define PREP_BLKS (KNN_BLKS + TR_BLKS + CP1_BLKS + SW_BLKS)

// ---------------- scratch ----------------------------------------------------
__device__ int   g_idx[Bb_ * N1_ * KNN_];
__device__ float g_w  [Bb_ * N1_ * KNN_];
__device__ float g_p2t[(size_t)Bb_ * N2_ * C2_];
__device__ float g_y0 [(size_t)Bb_ * M0_ * N1_];
__device__ __nv_bfloat16 g_x0h[(size_t)Bb_ * K0_ * N1_];
__device__ __nv_bfloat16 g_x0l[(size_t)Bb_ * K0_ * N1_];
__device__ float g_partS[M0_ * NSLOT];
__device__ float g_partQ[M0_ * NSLOT];
__device__ float g_scale0[M0_], g_shift0[M0_];
__device__ float g_scale1[M1_], g_shift1[M1_];
__device__ __nv_bfloat16 g_w0h[M0_ * K0_], g_w0l[M0_ * K0_];
__device__ __nv_bfloat16 g_w1h[M1_ * M0_], g_w1l[M1_ * M0_];

// ---------------- helpers -----------------------------------------------------
__device__ __forceinline__ uint32_t smem_u32(const void* p) {
    uint32_t a;
    asm("{ .reg .u64 t; cvta.to.shared.u64 t, %1; cvt.u32.u64 %0, t; }" : "=r"(a) : "l"(p));
    return a;
}
__device__ __forceinline__ void cp16(uint32_t dst, const void* src) {
    asm volatile("cp.async.cg.shared.global [%0], [%1], 16;" :: "r"(dst), "l"(src));
}
__device__ __forceinline__ void cp_commit() { asm volatile("cp.async.commit_group;" ::: "memory"); }
__device__ __forceinline__ void cp_wait1()  { asm volatile("cp.async.wait_group 1;" ::: "memory"); }
__device__ __forceinline__ void ldsm_x4(uint32_t* r, uint32_t addr) {
    asm volatile("ldmatrix.sync.aligned.m8n8.x4.shared.b16 {%0,%1,%2,%3}, [%4];"
                 : "=r"(r[0]), "=r"(r[1]), "=r"(r[2]), "=r"(r[3]) : "r"(addr));
}
__device__ __forceinline__ void ldsm_x4t(uint32_t* r, uint32_t addr) {
    asm volatile("ldmatrix.sync.aligned.m8n8.x4.trans.shared.b16 {%0,%1,%2,%3}, [%4];"
                 : "=r"(r[0]), "=r"(r[1]), "=r"(r[2]), "=r"(r[3]) : "r"(addr));
}
__device__ __forceinline__ void mma_bf16(float* d, const uint32_t* a, const uint32_t* b) {
    asm volatile("mma.sync.aligned.m16n8k16.row.col.f32.bf16.bf16.f32 "
                 "{%0,%1,%2,%3}, {%4,%5,%6,%7}, {%8,%9}, {%0,%1,%2,%3};"
                 : "+f"(d[0]), "+f"(d[1]), "+f"(d[2]), "+f"(d[3])
                 : "r"(a[0]), "r"(a[1]), "r"(a[2]), "r"(a[3]), "r"(b[0]), "r"(b[1]));
}
__device__ __forceinline__ uint32_t split_pack(float x0, float x1, uint32_t& lw) {
    __nv_bfloat16 h0 = __float2bfloat16_rn(x0);
    __nv_bfloat16 h1 = __float2bfloat16_rn(x1);
    __nv_bfloat16 l0 = __float2bfloat16_rn(x0 - __bfloat162float(h0));
    __nv_bfloat16 l1 = __float2bfloat16_rn(x1 - __bfloat162float(h1));
    lw = (uint32_t)__bfloat16_as_ushort(l0) | ((uint32_t)__bfloat16_as_ushort(l1) << 16);
    return (uint32_t)__bfloat16_as_ushort(h0) | ((uint32_t)__bfloat16_as_ushort(h1) << 16);
}

// ---------------- kernel 1: fused prep (knn | transpose | convp1 | splitw) ----
// Role decoded from blockIdx.x; knn blocks first so the long pole starts in
// wave 1 while memory-bound roles fill remaining SMs concurrently.
__global__ void __launch_bounds__(256) prep_kernel(
    const float* __restrict__ xyz1, const float* __restrict__ xyz2,
    const float* __restrict__ points1, const float* __restrict__ points2,
    const float* __restrict__ W0, const float* __restrict__ W1)
{
    __shared__ float smem[4 * N2_];   // 16 KB; knn uses all, transpose uses 4.2 KB
    const int id  = blockIdx.x;
    const int tid = threadIdx.x;

    if (id < KNN_BLKS) {
        // ---- 3-NN: block = 512 points (2 per thread), batch b ----
        float* sx = smem;           float* sy = smem + N2_;
        float* sz = smem + 2*N2_;   float* ss = smem + 3*N2_;
        const int b  = id >> 3;
        const int bx = id & 7;
        const float* p2 = xyz2 + (size_t)b * N2_ * 3;
        for (int j = tid; j < N2_; j += 256) {
            float x = p2[j*3+0], y = p2[j*3+1], z = p2[j*3+2];
            sx[j] = x; sy[j] = y; sz[j] = z; ss[j] = x*x + y*y + z*z;
        }
        __syncthreads();

        const int na = bx * 512 + tid;
        const int nb = na + 256;
        const float* pa = xyz1 + ((size_t)b * N1_ + na) * 3;
        const float* pb = xyz1 + ((size_t)b * N1_ + nb) * 3;
        const float xa = pa[0], ya = pa[1], za = pa[2];
        const float xb = pb[0], yb = pb[1], zb = pb[2];
        const float s1a = xa*xa + ya*ya + za*za;
        const float s1b = xb*xb + yb*yb + zb*zb;

        float a0 = 3.0e38f, a1 = 3.0e38f, a2 = 3.0e38f;
        float b0 = 3.0e38f, b1 = 3.0e38f, b2 = 3.0e38f;
        int   ia0 = 0, ia1 = 0, ia2 = 0;
        int   ib0 = 0, ib1 = 0, ib2 = 0;
        #pragma unroll 4
        for (int j = 0; j < N2_; j++) {
            const float cx = sx[j], cy = sy[j], cz = sz[j], cs = ss[j];
            float da = fmaxf(s1a + cs - 2.0f * (xa*cx + ya*cy + za*cz), EPSD);
            float db = fmaxf(s1b + cs - 2.0f * (xb*cx + yb*cy + zb*cz), EPSD);
            if (da < a2) {
                if (da < a1) {
                    a2 = a1; ia2 = ia1;
                    if (da < a0) { a1 = a0; ia1 = ia0; a0 = da; ia0 = j; }
                    else         { a1 = da; ia1 = j; }
                } else { a2 = da; ia2 = j; }
            }
            if (db < b2) {
                if (db < b1) {
                    b2 = b1; ib2 = ib1;
                    if (db < b0) { b1 = b0; ib1 = ib0; b0 = db; ib0 = j; }
                    else         { b1 = db; ib1 = j; }
                } else { b2 = db; ib2 = j; }
            }
        }
        {
            float w0 = 1.0f/a0, w1 = 1.0f/a1, w2 = 1.0f/a2;
            float inv = 1.0f / (w0 + w1 + w2);
            size_t base = ((size_t)b * N1_ + na) * KNN_;
            g_idx[base+0] = ia0; g_idx[base+1] = ia1; g_idx[base+2] = ia2;
            g_w  [base+0] = w0*inv; g_w[base+1] = w1*inv; g_w[base+2] = w2*inv;
        }
        {
            float w0 = 1.0f/b0, w1 = 1.0f/b1, w2 = 1.0f/b2;
            float inv = 1.0f / (w0 + w1 + w2);
            size_t base = ((size_t)b * N1_ + nb) * KNN_;
            g_idx[base+0] = ib0; g_idx[base+1] = ib1; g_idx[base+2] = ib2;
            g_w  [base+0] = w0*inv; g_w[base+1] = w1*inv; g_w[base+2] = w2*inv;
        }
    } else if (id < KNN_BLKS + TR_BLKS) {
        // ---- transpose points2 (C2,N2) -> (N2,C2) ----
        const int id2 = id - KNN_BLKS;
        const int n0 = (id2 & 31) * 32;
        const int c0 = ((id2 >> 5) & 7) * 32;
        const int b  = id2 >> 8;
        float (*tile)[33] = (float(*)[33])smem;
        const int tx = tid & 31, ty = tid >> 5;
        const float* s = points2 + (size_t)b * C2_ * N2_;
        #pragma unroll
        for (int i = 0; i < 4; i++)
            tile[ty + i*8][tx] = s[(size_t)(c0 + ty + i*8) * N2_ + n0 + tx];
        __syncthreads();
        float* d = g_p2t + (size_t)b * N2_ * C2_;
        #pragma unroll
        for (int i = 0; i < 4; i++)
            d[(size_t)(n0 + ty + i*8) * C2_ + c0 + tx] = tile[tx][ty + i*8];
    } else if (id < KNN_BLKS + TR_BLKS + CP1_BLKS) {
        // ---- convp1: points1 -> x0 rows [0..128) as bf16 h/l ----
        const int idx = (id - KNN_BLKS - TR_BLKS) * 256 + tid;   // float4 index
        const int n4 = idx & 1023;
        const int c  = (idx >> 10) & (C1_ - 1);
        const int b  = idx >> 17;
        float4 v = *(const float4*)(points1 + (((size_t)b * C1_ + c) * N1_) + n4*4);
        uint32_t h0, h1, l0, l1;
        h0 = split_pack(v.x, v.y, l0);
        h1 = split_pack(v.z, v.w, l1);
        const size_t di = ((size_t)b * K0_ + c) * N1_ + n4*4;
        *(uint2*)(g_x0h + di) = make_uint2(h0, h1);
        *(uint2*)(g_x0l + di) = make_uint2(l0, l1);
    } else {
        // ---- splitw: weights fp32 -> bf16 h/l ----
        const int i = (id - KNN_BLKS - TR_BLKS - CP1_BLKS) * 256 + tid;
        if (i < M0_ * K0_) {
            float v = W0[i];
            __nv_bfloat16 h = __float2bfloat16_rn(v);
            g_w0h[i] = h;
            g_w0l[i] = __float2bfloat16_rn(v - __bfloat162float(h));
        }
        if (i < M1_ * M0_) {
            float v = W1[i];
            __nv_bfloat16 h = __float2bfloat16_rn(v);
            g_w1h[i] = h;
            g_w1l[i] = __float2bfloat16_rn(v - __bfloat162float(h));
        }
    }
}

// ---------------- kernel 2: interpolate (point-major gathers) ----------------
__global__ void __launch_bounds__(256) interp_kernel()
{
    __shared__ uint16_t shh[256][34];
    __shared__ uint16_t shl[256][34];
    __shared__ int   sj[96];
    __shared__ float swt[96];

    const int b  = blockIdx.y;
    const int n0 = blockIdx.x * 32;
    const int t  = threadIdx.x;
    const int lane = t & 31, w = t >> 5;

    if (t < 96) {
        const size_t kb = ((size_t)b * N1_ + n0) * KNN_;
        sj[t]  = g_idx[kb + t];
        swt[t] = g_w[kb + t];
    }
    __syncthreads();

    #pragma unroll
    for (int it = 0; it < 4; it++) {
        const int p = w + it * 8;
        const int   j0 = sj[p*3],  j1 = sj[p*3+1],  j2 = sj[p*3+2];
        const float w0 = swt[p*3], w1 = swt[p*3+1], w2 = swt[p*3+2];
        const float* r0 = g_p2t + ((size_t)b * N2_ + j0) * C2_;
        const float* r1 = g_p2t + ((size_t)b * N2_ + j1) * C2_;
        const float* r2 = g_p2t + ((size_t)b * N2_ + j2) * C2_;
        #pragma unroll
        for (int i = 0; i < 8; i++) {
            const int c = i * 32 + lane;
            float v = w0 * r0[c] + w1 * r1[c] + w2 * r2[c];
            __nv_bfloat16 h  = __float2bfloat16_rn(v);
            __nv_bfloat16 lo = __float2bfloat16_rn(v - __bfloat162float(h));
            shh[c][p] = __bfloat16_as_ushort(h);
            shl[c][p] = __bfloat16_as_ushort(lo);
        }
    }
    __syncthreads();

    #pragma unroll 4
    for (int k = 0; k < 32; k++) {
        const int c = w * 32 + k;
        const size_t di = ((size_t)b * K0_ + C1_ + c) * N1_ + n0 + lane;
        g_x0h[di] = __ushort_as_bfloat16(shh[c][lane]);
        g_x0l[di] = __ushort_as_bfloat16(shl[c][lane]);
    }
}

// ---------------- kernel 3: split-bf16 mma.sync GEMM (128m x 256n) -----------
// BN_IN=false: B staged via cp.async from bf16 h/l (GEMM0).
// BN_IN=true:  B staged from fp32 Xf with fused BN+ReLU+split (GEMM1).
template<bool BN_IN>
__global__ void __launch_bounds__(256, 1) mma_gemm(
    const __nv_bfloat16* __restrict__ Wh, const __nv_bfloat16* __restrict__ Wl,
    int Mdim, int Kdim,
    const __nv_bfloat16* __restrict__ Xh, const __nv_bfloat16* __restrict__ Xl,
    const float* __restrict__ Xf,
    const float* __restrict__ bnsc, const float* __restrict__ bnsh,
    const float* __restrict__ bias,
    float* __restrict__ Y)
{
    constexpr int BMT = 128, BNT = 256;
    constexpr uint32_t B_STRT = (uint32_t)(BNT * 2 + 16);      // 528
    constexpr uint32_t SZ_AT  = (uint32_t)BMT * A_STR;         // 10240
    constexpr uint32_t SZ_BT  = 32u * B_STRT;                  // 16896
    constexpr uint32_t OFF_AL = SZ_AT;
    constexpr uint32_t OFF_BH = 2u * SZ_AT;
    constexpr uint32_t OFF_BL = OFF_BH + SZ_BT;
    constexpr uint32_t BUF_SZ = 2u * SZ_AT + 2u * SZ_BT;       // 54272

    extern __shared__ __align__(16) char sm[];
    const uint32_t sbase = smem_u32(sm);

    const int tid = threadIdx.x;
    const int lane = tid & 31, wid = tid >> 5;
    const int wm = wid >> 2, wn = wid & 3;          // 2m x 4n warps, 64x64 tiles
    const int bb = blockIdx.z;
    const int m0 = blockIdx.y * BMT;
    const int n0 = blockIdx.x * BNT;
    const size_t xbase = (size_t)bb * Kdim * N1_;
    const int T = Kdim / BK;

    auto stage = [&](int t, int buf) {
        const int kt = t * BK;
        const uint32_t bufb = sbase + (uint32_t)buf * BUF_SZ;
        #pragma unroll
        for (int q = 0; q < 2; q++) {
            const int c = tid + q * 256;
            const int row = c >> 2, off = c & 3;
            const size_t so = (size_t)(m0 + row) * Kdim + kt + off * 8;
            const uint32_t dd = bufb + (uint32_t)row * A_STR + off * 16;
            cp16(dd,          Wh + so);
            cp16(dd + OFF_AL, Wl + so);
        }
        if (!BN_IN) {
            #pragma unroll
            for (int q = 0; q < 4; q++) {
                const int c = tid + q * 256;
                const int row = c >> 5, off = c & 31;
                const size_t so = xbase + (size_t)(kt + row) * N1_ + n0 + off * 8;
                const uint32_t dd = bufb + OFF_BH + (uint32_t)row * B_STRT + off * 16;
                cp16(dd,                     Xh + so);
                cp16(dd + (OFF_BL - OFF_BH), Xl + so);
            }
        }
        cp_commit();
    };

    float vreg[32];
    const int br  = tid >> 3;
    const int bc0 = (tid & 7) * 4;
    auto ldB_bn = [&](int t) {
        if (!BN_IN || t >= T) return;
        const float* src = Xf + xbase + (size_t)(t * BK + br) * N1_ + n0 + bc0;
        #pragma unroll
        for (int q = 0; q < 8; q++)
            *(float4*)(vreg + 4*q) = *(const float4*)(src + q * 32);
    };
    auto stB_bn = [&](int t, int buf) {
        if (!BN_IN || t >= T) return;
        const int k = t * BK + br;
        const float sc = bnsc[k], so = bnsh[k];
        char* dh = sm + (size_t)buf * BUF_SZ + OFF_BH + (size_t)br * B_STRT + (tid & 7) * 8;
        #pragma unroll
        for (int q = 0; q < 8; q++) {
            float x0 = fmaxf(fmaf(sc, vreg[4*q+0], so), 0.0f);
            float x1 = fmaxf(fmaf(sc, vreg[4*q+1], so), 0.0f);
            float x2 = fmaxf(fmaf(sc, vreg[4*q+2], so), 0.0f);
            float x3 = fmaxf(fmaf(sc, vreg[4*q+3], so), 0.0f);
            uint32_t l0, l1;
            uint32_t h0 = split_pack(x0, x1, l0);
            uint32_t h1 = split_pack(x2, x3, l1);
            *(uint2*)(dh + q*64)                     = make_uint2(h0, h1);
            *(uint2*)(dh + q*64 + (OFF_BL - OFF_BH)) = make_uint2(l0, l1);
        }
    };

    float acc[4][8][4];
    #pragma unroll
    for (int i = 0; i < 4; i++)
        #pragma unroll
        for (int j = 0; j < 8; j++)
            #pragma unroll
            for (int q = 0; q < 4; q++) acc[i][j][q] = 0.0f;

    const uint32_t a_rowoff = (uint32_t)(wm*64 + (lane & 15)) * A_STR + ((lane >> 4) * 16);
    const uint32_t b_rowoff = (uint32_t)(lane & 15) * B_STRT + (uint32_t)wn*128 + ((lane >> 4) * 16);

    stage(0, 0);
    stage(1, 1);
    if (BN_IN) {
        ldB_bn(0); stB_bn(0, 0);
        ldB_bn(1);
    }

    for (int t = 0; t < T; t++) {
        cp_wait1();
        __syncthreads();
        if (t + 2 < T) stage(t + 2, (t + 2) % NSTAGE);
        else           cp_commit();
        if (BN_IN) {
            stB_bn(t + 1, (t + 1) % NSTAGE);
            ldB_bn(t + 2);
        }

        const uint32_t cb = sbase + (uint32_t)(t % NSTAGE) * BUF_SZ;
        #pragma unroll
        for (int kh = 0; kh < 2; kh++) {
            uint32_t ah[4][4], al[4][4];
            #pragma unroll
            for (int i = 0; i < 4; i++) {
                const uint32_t addr = cb + a_rowoff + (uint32_t)i*16*A_STR + kh*32;
                ldsm_x4(ah[i], addr);
                ldsm_x4(al[i], addr + OFF_AL);
            }
            #pragma unroll
            for (int j2 = 0; j2 < 4; j2++) {
                uint32_t rh[4], rl[4];
                const uint32_t baddr = cb + OFF_BH + b_rowoff + (uint32_t)kh*16*B_STRT + j2*32;
                ldsm_x4t(rh, baddr);
                ldsm_x4t(rl, baddr + (OFF_BL - OFF_BH));
                #pragma unroll
                for (int i = 0; i < 4; i++) {
                    mma_bf16(acc[i][2*j2],   ah[i], rh);
                    mma_bf16(acc[i][2*j2],   al[i], rh);
                    mma_bf16(acc[i][2*j2],   ah[i], rl);
                    mma_bf16(acc[i][2*j2+1], ah[i], rh + 2);
                    mma_bf16(acc[i][2*j2+1], al[i], rh + 2);
                    mma_bf16(acc[i][2*j2+1], ah[i], rl + 2);
                }
            }
        }
        __syncthreads();
    }

    // ---- epilogue: bias add + fp32 store + per-row partial stats ----
    float* SS = (float*)sm;                  // [4 wn][128 rows]
    float* SQ = (float*)sm + 4*128;

    #pragma unroll
    for (int i = 0; i < 4; i++) {
        const int lr0 = wm*64 + i*16 + (lane >> 2);
        const int r0 = m0 + lr0;
        const int r1 = r0 + 8;
        const float bv0 = bias[r0], bv1 = bias[r1];
        float* y0p = Y + ((size_t)bb * Mdim + r0) * N1_ + n0 + wn*64;
        float* y1p = Y + ((size_t)bb * Mdim + r1) * N1_ + n0 + wn*64;
        float sa = 0.f, qa = 0.f, sb = 0.f, qb = 0.f;
        #pragma unroll
        for (int j = 0; j < 8; j++) {
            const int nc = j*8 + (lane & 3)*2;
            float v0 = acc[i][j][0] + bv0, v1 = acc[i][j][1] + bv0;
            float v2 = acc[i][j][2] + bv1, v3 = acc[i][j][3] + bv1;
            *(float2*)(y0p + nc) = make_float2(v0, v1);
            *(float2*)(y1p + nc) = make_float2(v2, v3);
            sa += v0 + v1; qa += v0*v0 + v1*v1;
            sb += v2 + v3; qb += v2*v2 + v3*v3;
        }
        #pragma unroll
        for (int o = 1; o < 4; o <<= 1) {
            sa += __shfl_xor_sync(0xffffffffu, sa, o);
            qa += __shfl_xor_sync(0xffffffffu, qa, o);
            sb += __shfl_xor_sync(0xffffffffu, sb, o);
            qb += __shfl_xor_sync(0xffffffffu, qb, o);
        }
        if ((lane & 3) == 0) {
            SS[wn*128 + lr0]     = sa;  SQ[wn*128 + lr0]     = qa;
            SS[wn*128 + lr0 + 8] = sb;  SQ[wn*128 + lr0 + 8] = qb;
        }
    }
    __syncthreads();
    if (tid < 128) {
        const float s = SS[tid] + SS[128+tid] + SS[256+tid] + SS[384+tid];
        const float q = SQ[tid] + SQ[128+tid] + SQ[256+tid] + SQ[384+tid];
        const int slot = bb * 16 + blockIdx.x;
        g_partS[(size_t)(m0 + tid) * NSLOT + slot] = s;
        g_partQ[(size_t)(m0 + tid) * NSLOT + slot] = q;
    }
}

// ---------------- kernel 4: finalize scale/shift (block per channel) ---------
__global__ void __launch_bounds__(256) stats_final_kernel(const float* __restrict__ gamma,
                                                          const float* __restrict__ beta,
                                                          int layer)
{
    const int c = blockIdx.x;
    const int t = threadIdx.x;
    __shared__ float sh[256], sh2[256];
    sh[t]  = g_partS[(size_t)c * NSLOT + t];
    sh2[t] = g_partQ[(size_t)c * NSLOT + t];
    __syncthreads();
    for (int o = 128; o > 0; o >>= 1) {
        if (t < o) { sh[t] += sh[t + o]; sh2[t] += sh2[t + o]; }
        __syncthreads();
    }
    if (t == 0) {
        const float cnt = (float)(Bb_ * N1_);
        float m = sh[0] / cnt;
        float v = sh2[0] / cnt - m * m;
        float r = rsqrtf(v + BNEPS);
        float a = gamma[c] * r;
        if (layer == 0) { g_scale0[c] = a; g_shift0[c] = beta[c] - a * m; }
        else            { g_scale1[c] = a; g_shift1[c] = beta[c] - a * m; }
    }
}

// ---------------- kernel 5: BN1 + ReLU in place ------------------------------
__global__ void __launch_bounds__(256) bnrelu_kernel(float* __restrict__ Yv, int Mdim)
{
    const size_t total4 = (size_t)Bb_ * Mdim * N1_ / 4;
    const size_t i = (size_t)blockIdx.x * blockDim.x + threadIdx.x;
    if (i >= total4) return;
    const int c = (int)((i >> 10) % Mdim);
    const float a  = g_scale1[c];
    const float sh = g_shift1[c];
    float4 v = ((float4*)Yv)[i];
    v.x = fmaxf(fmaf(a, v.x, sh), 0.0f);
    v.y = fmaxf(fmaf(a, v.y, sh), 0.0f);
    v.z = fmaxf(fmaf(a, v.z, sh), 0.0f);
    v.w = fmaxf(fmaf(a, v.w, sh), 0.0f);
    ((float4*)Yv)[i] = v;
}

// ---------------- launch ------------------------------------------------------
extern "C" void kernel_launch(void* const* d_in, const int* in_sizes, int n_in,
                              void* d_out, int out_size)
{
    const float* xyz1    = (const float*)d_in[0];
    const float* xyz2    = (const float*)d_in[1];
    const float* points1 = (const float*)d_in[2];
    const float* points2 = (const float*)d_in[3];
    const float* W0 = (const float*)d_in[4];
    const float* b0 = (const float*)d_in[5];
    const float* g0 = (const float*)d_in[6];
    const float* be0= (const float*)d_in[7];
    const float* W1 = (const float*)d_in[8];
    const float* b1 = (const float*)d_in[9];
    const float* g1 = (const float*)d_in[10];
    const float* be1= (const float*)d_in[11];
    float* out = (float*)d_out;

    void* p;
    cudaGetSymbolAddress(&p, g_y0);      float* y0 = (float*)p;
    cudaGetSymbolAddress(&p, g_x0h);     __nv_bfloat16* x0h = (__nv_bfloat16*)p;
    cudaGetSymbolAddress(&p, g_x0l);     __nv_bfloat16* x0l = (__nv_bfloat16*)p;
    cudaGetSymbolAddress(&p, g_w0h);     __nv_bfloat16* w0h = (__nv_bfloat16*)p;
    cudaGetSymbolAddress(&p, g_w0l);     __nv_bfloat16* w0l = (__nv_bfloat16*)p;
    cudaGetSymbolAddress(&p, g_w1h);     __nv_bfloat16* w1h = (__nv_bfloat16*)p;
    cudaGetSymbolAddress(&p, g_w1l);     __nv_bfloat16* w1l = (__nv_bfloat16*)p;
    cudaGetSymbolAddress(&p, g_scale0);  float* sc0 = (float*)p;
    cudaGetSymbolAddress(&p, g_shift0);  float* sh0 = (float*)p;

    const unsigned SMEM_GEMM = NSTAGE * (2u*(128u*A_STR) + 2u*(32u*528u));  // 162816
    cudaFuncSetAttribute((const void*)mma_gemm<false>, cudaFuncAttributeMaxDynamicSharedMemorySize, SMEM_GEMM);
    cudaFuncSetAttribute((const void*)mma_gemm<true>,  cudaFuncAttributeMaxDynamicSharedMemorySize, SMEM_GEMM);

    // 0. fused prep: knn | transpose | convp1 | splitw (concurrent roles)
    prep_kernel<<<PREP_BLKS, 256>>>(xyz1, xyz2, points1, points2, W0, W1);

    // 1. interpolation (needs knn + transpose)
    interp_kernel<<<dim3(N1_/32, Bb_), 256>>>();

    // 2. GEMM0 (+fused stats): [256 x 384] @ [384 x N] + b0 -> y0
    mma_gemm<false><<<dim3(N1_/256, M0_/128, Bb_), 256, SMEM_GEMM>>>(
        w0h, w0l, M0_, K0_, x0h, x0l, nullptr, nullptr, nullptr, b0, y0);

    // 3. finalize BN0
    stats_final_kernel<<<M0_, 256>>>(g0, be0, 0);

    // 4. GEMM1 with fused BN0+ReLU+split input (+fused stats): -> out
    mma_gemm<true><<<dim3(N1_/256, M1_/128, Bb_), 256, SMEM_GEMM>>>(
        w1h, w1l, M1_, M0_, nullptr, nullptr, y0, sc0, sh0, b1, out);

    // 5. finalize BN1 + apply in place
    stats_final_kernel<<<M1_, 256>>>(g1, be1, 1);
    {
        size_t total4 = (size_t)Bb_ * M1_ * N1_ / 4;
        bnrelu_kernel<<<(unsigned)((total4 + 255) / 256), 256>>>(out, M1_);
    }
}